// round 1
// baseline (speedup 1.0000x reference)
#include <cuda_runtime.h>
#include <math.h>

#define BB 16
#define TT 32
#define PP 14
#define HH 12
#define DD 64
#define LL 196
#define DMODEL 768
#define SS 16

// ---------------- scratch (device globals; no allocation allowed) -------------
__device__ float g_aff0[(size_t)BB * LL * 1024];   // conv1 output (B,P,P,1024)
__device__ float g_y1[(size_t)BB * LL * 1024];     // after MLP residual
__device__ float g_ypart[(size_t)BB * TT * DMODEL]; // per-(b,t) spatial partials

// =============================================================================
// Kernel 1: temporal gram + softmax + 24ch->1 3x3 conv, fused per (b,l) block.
// smem: xsT[4 heads][64 d][33 (padded t)] reused as gm[4][32][32] after gram
// regs: 4x4 gram tile per thread; conv accumulators live in registers.
// =============================================================================
__global__ __launch_bounds__(256) void k1_gram(
    const float* __restrict__ qp, const float* __restrict__ kp,
    const float* __restrict__ tw, const float* __restrict__ tb)
{
    __shared__ float sm1[4 * 64 * 33];          // 33792 B
    float* gm = sm1;                            // reuse as [4][32][32]

    const int tid = threadIdx.x;
    const int bl = blockIdx.x;
    const int b = bl / LL, l = bl % LL;

    const int warp = tid >> 5, lane = tid & 31;
    const int g4 = tid >> 6, tt = tid & 63;
    const int q0 = (tt >> 3) << 2, k0 = (tt & 7) << 2;

    float racc[4] = {0.f, 0.f, 0.f, 0.f};       // conv accumulators (idx = tid+u*256)

    for (int chunk = 0; chunk < 6; chunk++) {
        // ---- load 4 heads' x = a[b, t, 1+l, h, :] transposed -> xsT[g][d][t]
        #pragma unroll
        for (int g = 0; g < 4; g++) {
            int c = chunk * 4 + g;
            const float* src = (c < HH) ? qp : kp;
            int h = c % HH;
            const float* base = src + ((size_t)b * TT * 197 + (l + 1)) * DMODEL + h * DD;
            #pragma unroll
            for (int j = 0; j < 8; j++) {
                int idx = tid + j * 256;
                int t = idx >> 6, d = idx & 63;
                sm1[(g * 64 + d) * 33 + t] = base[(size_t)t * 197 * DMODEL + d];
            }
        }
        __syncthreads();

        // ---- gram: 4x4 register tile per thread (64 threads per head)
        float s[4][4];
        #pragma unroll
        for (int i = 0; i < 4; i++)
            #pragma unroll
            for (int j = 0; j < 4; j++) s[i][j] = 0.f;
        {
            const float* xg = sm1 + g4 * 64 * 33;
            #pragma unroll 8
            for (int d = 0; d < 64; d++) {
                float aq[4], ak[4];
                #pragma unroll
                for (int i = 0; i < 4; i++) aq[i] = xg[d * 33 + q0 + i];
                #pragma unroll
                for (int j = 0; j < 4; j++) ak[j] = xg[d * 33 + k0 + j];
                #pragma unroll
                for (int i = 0; i < 4; i++)
                    #pragma unroll
                    for (int j = 0; j < 4; j++) s[i][j] = fmaf(aq[i], ak[j], s[i][j]);
            }
        }
        __syncthreads();   // everyone done reading xsT before gm overwrites it

        #pragma unroll
        for (int i = 0; i < 4; i++)
            #pragma unroll
            for (int j = 0; j < 4; j++)
                gm[(g4 * 32 + q0 + i) * 32 + k0 + j] = s[i][j] * 0.125f;  // scale = 1/sqrt(64)
        __syncthreads();

        // ---- softmax over k (row-wise), 128 rows, warp-per-row strided
        #pragma unroll
        for (int m = 0; m < 16; m++) {
            int r = warp + (m << 3);
            float v = gm[r * 32 + lane];
            float mx = v;
            #pragma unroll
            for (int o = 16; o > 0; o >>= 1) mx = fmaxf(mx, __shfl_xor_sync(0xffffffffu, mx, o));
            float e = __expf(v - mx);
            float ss = e;
            #pragma unroll
            for (int o = 16; o > 0; o >>= 1) ss += __shfl_xor_sync(0xffffffffu, ss, o);
            gm[r * 32 + lane] = e / ss;
        }
        __syncthreads();

        // ---- conv accumulate (cross-correlation, SAME padding)
        {
            float wreg[4][9];
            #pragma unroll
            for (int g = 0; g < 4; g++)
                #pragma unroll
                for (int j = 0; j < 9; j++) wreg[g][j] = tw[(chunk * 4 + g) * 9 + j];
            #pragma unroll
            for (int u = 0; u < 4; u++) {
                int idx = tid + u * 256;
                int t1 = idx >> 5, t2 = idx & 31;
                float r = 0.f;
                #pragma unroll
                for (int g = 0; g < 4; g++) {
                    const float* gg = gm + g * 1024;
                    #pragma unroll
                    for (int dy = 0; dy < 3; dy++) {
                        int y = t1 + dy - 1;
                        if ((unsigned)y >= 32u) continue;
                        #pragma unroll
                        for (int dx = 0; dx < 3; dx++) {
                            int x = t2 + dx - 1;
                            if ((unsigned)x >= 32u) continue;
                            r = fmaf(gg[y * 32 + x], wreg[g][dy * 3 + dx], r);
                        }
                    }
                }
                racc[u] += r;
            }
        }
        __syncthreads();
    }

    float bias = tb[0];
    #pragma unroll
    for (int u = 0; u < 4; u++) {
        int idx = tid + u * 256;
        g_aff0[(size_t)bl * 1024 + idx] = racc[u] + bias;
    }
}

// =============================================================================
// Kernel 2: LayerNorm(1024) + Linear(1024->32) + exact GELU + Linear(32->1024)
//           + residual, one (b,p1,p2) row per block.
// =============================================================================
__global__ __launch_bounds__(256) void k2_mlp(
    const float* __restrict__ lng, const float* __restrict__ lnb,
    const float* __restrict__ w1, const float* __restrict__ b1,
    const float* __restrict__ w2, const float* __restrict__ b2)
{
    __shared__ float xr[1024];
    __shared__ float xn[1024];
    __shared__ float part[32][9];
    __shared__ float g1[32];
    __shared__ float red[2][8];

    const int tid = threadIdx.x;
    const int warp = tid >> 5, lane = tid & 31;
    const size_t base = (size_t)blockIdx.x * 1024;

    float s1 = 0.f, s2 = 0.f;
    #pragma unroll
    for (int u = 0; u < 4; u++) {
        int i = tid + u * 256;
        float v = g_aff0[base + i];
        xr[i] = v; s1 += v; s2 += v * v;
    }
    #pragma unroll
    for (int o = 16; o > 0; o >>= 1) {
        s1 += __shfl_xor_sync(0xffffffffu, s1, o);
        s2 += __shfl_xor_sync(0xffffffffu, s2, o);
    }
    if (lane == 0) { red[0][warp] = s1; red[1][warp] = s2; }
    __syncthreads();
    float a = 0.f, bq = 0.f;
    #pragma unroll
    for (int i = 0; i < 8; i++) { a += red[0][i]; bq += red[1][i]; }
    float mean = a * (1.f / 1024.f);
    float var = bq * (1.f / 1024.f) - mean * mean;
    float rstd = rsqrtf(var + 1e-5f);

    #pragma unroll
    for (int u = 0; u < 4; u++) {
        int i = tid + u * 256;
        xn[i] = (xr[i] - mean) * rstd * lng[i] + lnb[i];
    }
    __syncthreads();

    // h = xn @ w1 : each warp covers 128 i-rows, lane = output j (coalesced w1)
    {
        float acc = 0.f;
        int i0 = warp * 128;
        #pragma unroll 8
        for (int i = 0; i < 128; i++) acc = fmaf(xn[i0 + i], w1[(i0 + i) * 32 + lane], acc);
        part[lane][warp] = acc;
    }
    __syncthreads();
    if (tid < 32) {
        float h = b1[tid];
        #pragma unroll
        for (int w = 0; w < 8; w++) h += part[tid][w];
        g1[tid] = 0.5f * h * (1.0f + erff(h * 0.70710678118654752f));  // exact GELU
    }
    __syncthreads();

    #pragma unroll
    for (int u = 0; u < 4; u++) {
        int i = tid + u * 256;
        float o = xr[i] + b2[i];
        #pragma unroll 8
        for (int j = 0; j < 32; j++) o = fmaf(g1[j], w2[j * 1024 + i], o);
        g_y1[base + i] = o;
    }
}

// =============================================================================
// Kernel 3: p_conv 1024ch -> 1, 3x3 SAME over (P,P); one output per block.
// =============================================================================
__global__ __launch_bounds__(256) void k3_pconv(
    const float* __restrict__ pw, const float* __restrict__ pb,
    float* __restrict__ out)
{
    __shared__ float red[8];
    const int tid = threadIdx.x;
    const int bi = blockIdx.x;
    const int b = bi / LL, l = bi % LL;
    const int p1 = l / PP, p2 = l % PP;

    float a = 0.f;
    #pragma unroll
    for (int dy = 0; dy < 3; dy++) {
        int y = p1 + dy - 1;
        if ((unsigned)y >= (unsigned)PP) continue;
        #pragma unroll
        for (int dx = 0; dx < 3; dx++) {
            int x = p2 + dx - 1;
            if ((unsigned)x >= (unsigned)PP) continue;
            const float* row = g_y1 + ((size_t)b * LL + y * PP + x) * 1024;
            #pragma unroll
            for (int m = 0; m < 4; m++) {
                int ch = tid + m * 256;
                a = fmaf(row[ch], pw[ch * 9 + dy * 3 + dx], a);
            }
        }
    }
    #pragma unroll
    for (int o = 16; o > 0; o >>= 1) a += __shfl_xor_sync(0xffffffffu, a, o);
    if ((tid & 31) == 0) red[tid >> 5] = a;
    __syncthreads();
    if (tid == 0) {
        float s = pb[0];
        #pragma unroll
        for (int w = 0; w < 8; w++) s += red[w];
        out[bi] = s;
    }
}

// =============================================================================
// Kernel 4: spatial syno attention per (b,t): scores (16x196, K=768) -> softmax
//           -> mix (16x768, K=196) -> sum over s into g_ypart.
// 4x4 register tiles everywhere; strided l/w per-thread assignment for
// conflict-free smem banks.
// =============================================================================
__global__ __launch_bounds__(256) void k4_spatial(
    const float* __restrict__ kp, const float* __restrict__ vp,
    const float* __restrict__ syno)
{
    __shared__ float sc[16][200];     // scores / probabilities
    __shared__ float buf[7168];       // kkT tiles (phase A) / v tiles (phase B) / reduce
    __shared__ float syT[32 * 16];    // syno d-chunk, transposed

    const int tid = threadIdx.x;
    const int bt = blockIdx.x;
    const float* kbase = kp + ((size_t)bt * 197 + 1) * DMODEL;
    const float* vbase = vp + ((size_t)bt * 197 + 1) * DMODEL;
    const float scale = 0.03608439182435161f;   // 1/sqrt(768)

    const int sg = tid / 49;     // 0..3 for active threads
    const int lg = tid % 49;
    const bool act = (tid < 196);

    float acc[4][4];
    #pragma unroll
    for (int i = 0; i < 4; i++)
        #pragma unroll
        for (int j = 0; j < 4; j++) acc[i][j] = 0.f;

    // ---- phase A: scores = (syno/sqrt(DM)) @ kk^T, chunked over d
    for (int dc = 0; dc < 24; dc++) {
        int d0 = dc * 32;
        for (int idx = tid; idx < 512; idx += 256) {
            int s = idx >> 5, dd = idx & 31;
            syT[dd * 16 + s] = syno[s * DMODEL + d0 + dd] * scale;
        }
        for (int idx = tid; idx < 6272; idx += 256) {
            int l = idx >> 5, dd = idx & 31;
            buf[dd * 197 + l] = kbase[(size_t)l * DMODEL + d0 + dd];
        }
        __syncthreads();
        if (act) {
            #pragma unroll 4
            for (int dd = 0; dd < 32; dd++) {
                float sa[4], ka[4];
                #pragma unroll
                for (int i = 0; i < 4; i++) sa[i] = syT[dd * 16 + sg + 4 * i];
                #pragma unroll
                for (int j = 0; j < 4; j++) ka[j] = buf[dd * 197 + lg + 49 * j];
                #pragma unroll
                for (int i = 0; i < 4; i++)
                    #pragma unroll
                    for (int j = 0; j < 4; j++) acc[i][j] = fmaf(sa[i], ka[j], acc[i][j]);
            }
        }
        __syncthreads();
    }
    if (act) {
        #pragma unroll
        for (int i = 0; i < 4; i++)
            #pragma unroll
            for (int j = 0; j < 4; j++) sc[sg + 4 * i][lg + 49 * j] = acc[i][j];
    }
    __syncthreads();

    // ---- softmax over l (196) per syno row; warp handles 2 rows
    const int warp = tid >> 5, lane = tid & 31;
    #pragma unroll
    for (int si = 0; si < 2; si++) {
        int s = warp * 2 + si;
        float mx = -1e30f;
        for (int l = lane; l < 196; l += 32) mx = fmaxf(mx, sc[s][l]);
        #pragma unroll
        for (int o = 16; o > 0; o >>= 1) mx = fmaxf(mx, __shfl_xor_sync(0xffffffffu, mx, o));
        float sum = 0.f;
        for (int l = lane; l < 196; l += 32) {
            float e = __expf(sc[s][l] - mx);
            sc[s][l] = e; sum += e;
        }
        #pragma unroll
        for (int o = 16; o > 0; o >>= 1) sum += __shfl_xor_sync(0xffffffffu, sum, o);
        float inv = 1.f / sum;
        for (int l = lane; l < 196; l += 32) sc[s][l] *= inv;
    }
    __syncthreads();

    // ---- phase B: mix = p @ vv, summed over s, written per (b,t)
    const int wg = tid & 63, sg2 = tid >> 6;
    for (int wc = 0; wc < 3; wc++) {
        float mac[4][4];
        #pragma unroll
        for (int i = 0; i < 4; i++)
            #pragma unroll
            for (int j = 0; j < 4; j++) mac[i][j] = 0.f;
        for (int lc = 0; lc < 7; lc++) {
            for (int idx = tid; idx < 28 * 256; idx += 256) {
                int l = idx >> 8, ww = idx & 255;
                buf[l * 256 + ww] = vbase[(size_t)(lc * 28 + l) * DMODEL + wc * 256 + ww];
            }
            __syncthreads();
            #pragma unroll 4
            for (int ll = 0; ll < 28; ll++) {
                int l = lc * 28 + ll;
                float p[4], vvr[4];
                #pragma unroll
                for (int i = 0; i < 4; i++) p[i] = sc[sg2 + 4 * i][l];
                #pragma unroll
                for (int j = 0; j < 4; j++) vvr[j] = buf[ll * 256 + wg + 64 * j];
                #pragma unroll
                for (int i = 0; i < 4; i++)
                    #pragma unroll
                    for (int j = 0; j < 4; j++) mac[i][j] = fmaf(p[i], vvr[j], mac[i][j]);
            }
            __syncthreads();
        }
        #pragma unroll
        for (int j = 0; j < 4; j++)
            buf[sg2 * 256 + wg + 64 * j] = mac[0][j] + mac[1][j] + mac[2][j] + mac[3][j];
        __syncthreads();
        g_ypart[(size_t)bt * DMODEL + wc * 256 + tid] =
            buf[tid] + buf[256 + tid] + buf[512 + tid] + buf[768 + tid];
        __syncthreads();
    }
}

// =============================================================================
// Kernel 5: y_s[b][w] = mean over (t,s) -> sum partials over t / 512
// =============================================================================
__global__ __launch_bounds__(768) void k5_reduce(float* __restrict__ out)
{
    const int b = blockIdx.x, w = threadIdx.x;
    float s = 0.f;
    #pragma unroll
    for (int t = 0; t < 32; t++) s += g_ypart[((size_t)b * 32 + t) * DMODEL + w];
    out[b * DMODEL + w] = s * (1.f / 512.f);
}

// =============================================================================
extern "C" void kernel_launch(void* const* d_in, const int* in_sizes, int n_in,
                              void* d_out, int out_size)
{
    const float* q    = (const float*)d_in[0];
    const float* k    = (const float*)d_in[1];
    const float* v    = (const float*)d_in[2];
    const float* tw   = (const float*)d_in[3];
    const float* tb   = (const float*)d_in[4];
    const float* lng  = (const float*)d_in[5];
    const float* lnb  = (const float*)d_in[6];
    const float* w1   = (const float*)d_in[7];
    const float* b1   = (const float*)d_in[8];
    const float* w2   = (const float*)d_in[9];
    const float* b2   = (const float*)d_in[10];
    const float* pw   = (const float*)d_in[11];
    const float* pb   = (const float*)d_in[12];
    const float* syno = (const float*)d_in[13];
    float* out = (float*)d_out;

    k1_gram<<<BB * LL, 256>>>(q, k, tw, tb);
    k2_mlp<<<BB * LL, 256>>>(lng, lnb, w1, b1, w2, b2);
    k3_pconv<<<BB * LL, 256>>>(pw, pb, out);
    k4_spatial<<<BB * TT, 256>>>(k, v, syno);
    k5_reduce<<<BB, 768>>>(out + BB * LL);
}

// round 4
// speedup vs baseline: 1.1314x; 1.1314x over previous
#include <cuda_runtime.h>
#include <math.h>

#define BB 16
#define TT 32
#define PP 14
#define HH 12
#define DD 64
#define LL 196
#define DMODEL 768
#define SS 16

// ---------------- scratch (device globals; no allocation allowed) -------------
__device__ __align__(16) float g_aff0[(size_t)BB * LL * 1024];
__device__ __align__(16) float g_y1[(size_t)BB * LL * 1024];
__device__ __align__(16) float g_ypart[(size_t)BB * TT * DMODEL];

// ---------------- f32x2 packed-FMA helpers (sm_10x) ---------------------------
__device__ __forceinline__ unsigned long long pk2(float lo, float hi) {
    unsigned long long r;
    asm("mov.b64 %0, {%1, %2};" : "=l"(r) : "f"(lo), "f"(hi));
    return r;
}
__device__ __forceinline__ void upk2(unsigned long long v, float& lo, float& hi) {
    asm("mov.b64 {%0, %1}, %2;" : "=f"(lo), "=f"(hi) : "l"(v));
}
__device__ __forceinline__ void fma2(unsigned long long& d, unsigned long long a,
                                     unsigned long long b) {
    asm("fma.rn.f32x2 %0, %1, %2, %0;" : "+l"(d) : "l"(a), "l"(b));
}

// =============================================================================
// Kernel 1: temporal gram (f32x2, LDS.64 pairs) + softmax + 24ch->1 3x3 conv.
// smem xsT pad 34 (even -> LDS.64-aligned, 2-way write conflicts only).
// =============================================================================
__global__ __launch_bounds__(256) void k1_gram(
    const float* __restrict__ qp, const float* __restrict__ kp,
    const float* __restrict__ tw, const float* __restrict__ tb)
{
    __shared__ __align__(16) float sm1[4 * 64 * 34];   // 34816 B
    float* gm = sm1;                                   // alias: [4][32][32]

    const int tid = threadIdx.x;
    const int bl = blockIdx.x;
    const int b = bl / LL, l = bl % LL;

    const int warp = tid >> 5, lane = tid & 31;
    const int g4 = tid >> 6, tt = tid & 63;
    const int q0 = (tt >> 2) * 2;        // 2-row q tile
    const int k0 = (tt & 3) * 8;         // 8-col k tile
    const int ct1 = tid >> 3, ct2 = (tid & 7) * 4;   // conv: row, 4-col group

    float racc[4] = {0.f, 0.f, 0.f, 0.f};

    for (int chunk = 0; chunk < 6; chunk++) {
        // ---- load 4 heads, transposed [d][t], scaled by sqrt(1/8)
        #pragma unroll
        for (int g = 0; g < 4; g++) {
            int c = chunk * 4 + g;
            const float* src = (c < HH) ? qp : kp;
            int h = c % HH;
            const float* base = src + ((size_t)b * TT * 197 + (l + 1)) * DMODEL + h * DD;
            #pragma unroll
            for (int j = 0; j < 8; j++) {
                int idx = tid + j * 256;
                int t = idx >> 6, d = idx & 63;
                sm1[(g * 64 + d) * 34 + t] =
                    base[(size_t)t * 197 * DMODEL + d] * 0.35355339059327376f;
            }
        }
        __syncthreads();

        // ---- gram 2x8 tile: f32x2 accumulators
        unsigned long long acc[2][4] = {{0ull,0ull,0ull,0ull},{0ull,0ull,0ull,0ull}};
        {
            const float* xg = sm1 + g4 * (64 * 34);
            #pragma unroll 4
            for (int d = 0; d < 64; d++) {
                const float* row = xg + d * 34;
                float a0 = row[q0], a1 = row[q0 + 1];
                unsigned long long pa0 = pk2(a0, a0), pa1 = pk2(a1, a1);
                #pragma unroll
                for (int jp = 0; jp < 4; jp++) {
                    unsigned long long kpair =
                        *(const unsigned long long*)(row + k0 + 2 * jp);
                    fma2(acc[0][jp], pa0, kpair);
                    fma2(acc[1][jp], pa1, kpair);
                }
            }
        }
        __syncthreads();   // all reads of xsT done before gm overwrite

        #pragma unroll
        for (int i = 0; i < 2; i++)
            #pragma unroll
            for (int jp = 0; jp < 4; jp++)
                *(unsigned long long*)&gm[(g4 * 32 + q0 + i) * 32 + k0 + 2 * jp] =
                    acc[i][jp];
        __syncthreads();

        // ---- softmax over k, 128 rows
        #pragma unroll
        for (int m = 0; m < 16; m++) {
            int r = warp + (m << 3);
            float v = gm[r * 32 + lane];
            float mx = v;
            #pragma unroll
            for (int o = 16; o > 0; o >>= 1) mx = fmaxf(mx, __shfl_xor_sync(0xffffffffu, mx, o));
            float e = __expf(v - mx);
            float ss = e;
            #pragma unroll
            for (int o = 16; o > 0; o >>= 1) ss += __shfl_xor_sync(0xffffffffu, ss, o);
            gm[r * 32 + lane] = e * __fdividef(1.f, ss);
        }
        __syncthreads();

        // ---- conv accumulate: float4 windows, 4 outputs per thread along t2
        {
            float wreg[4][9];
            #pragma unroll
            for (int g = 0; g < 4; g++)
                #pragma unroll
                for (int j = 0; j < 9; j++) wreg[g][j] = tw[(chunk * 4 + g) * 9 + j];
            #pragma unroll
            for (int g = 0; g < 4; g++) {
                const float* gg = gm + g * 1024;
                #pragma unroll
                for (int dy = 0; dy < 3; dy++) {
                    int y = ct1 + dy - 1;
                    if ((unsigned)y >= 32u) continue;
                    float4 mid = *(const float4*)&gg[y * 32 + ct2];
                    float wl = (ct2 > 0)  ? gg[y * 32 + ct2 - 1] : 0.f;
                    float wr = (ct2 < 28) ? gg[y * 32 + ct2 + 4] : 0.f;
                    float win[6] = {wl, mid.x, mid.y, mid.z, mid.w, wr};
                    #pragma unroll
                    for (int dx = 0; dx < 3; dx++) {
                        float wt = wreg[g][dy * 3 + dx];
                        #pragma unroll
                        for (int m = 0; m < 4; m++)
                            racc[m] = fmaf(win[m + dx], wt, racc[m]);
                    }
                }
            }
        }
        __syncthreads();
    }

    float bias = tb[0];
    float4 o = make_float4(racc[0] + bias, racc[1] + bias, racc[2] + bias, racc[3] + bias);
    *(float4*)&g_aff0[(size_t)bl * 1024 + ct1 * 32 + ct2] = o;
}

// =============================================================================
// Kernel 2: LN + MLP + residual, 8 rows per block (w1/w2 L2 traffic / 8).
// =============================================================================
__global__ __launch_bounds__(256) void k2_mlp(
    const float* __restrict__ lng, const float* __restrict__ lnb,
    const float* __restrict__ w1, const float* __restrict__ b1,
    const float* __restrict__ w2, const float* __restrict__ b2)
{
    __shared__ __align__(16) float xnT[1024 * 8];   // [i][r]  32KB
    __shared__ float part[8 * 256];                 // [w][r*32+j]
    __shared__ float hs[256];                       // [r*32+j]
    __shared__ float mu[8], rs[8];

    const int tid = threadIdx.x;
    const int warp = tid >> 5, lane = tid & 31;
    const size_t R0 = (size_t)blockIdx.x * 8;

    // ---- stats: warp r
    {
        const float* xrow = g_aff0 + (R0 + warp) * 1024;
        float s1 = 0.f, s2 = 0.f;
        #pragma unroll 8
        for (int kk = 0; kk < 32; kk++) {
            float v = xrow[lane + 32 * kk];
            s1 += v; s2 += v * v;
        }
        #pragma unroll
        for (int o = 16; o > 0; o >>= 1) {
            s1 += __shfl_xor_sync(0xffffffffu, s1, o);
            s2 += __shfl_xor_sync(0xffffffffu, s2, o);
        }
        if (lane == 0) {
            float m = s1 * (1.f / 1024.f);
            float var = s2 * (1.f / 1024.f) - m * m;
            mu[warp] = m;
            rs[warp] = rsqrtf(var + 1e-5f);
        }
    }
    __syncthreads();

    // ---- normalize into xnT[i][r]
    for (int idx = tid; idx < 8192; idx += 256) {
        int r = idx >> 10, i = idx & 1023;
        float v = g_aff0[(R0 + r) * 1024 + i];
        xnT[i * 8 + r] = (v - mu[r]) * rs[r] * lng[i] + lnb[i];
    }
    __syncthreads();

    // ---- GEMM1: h[r][j] partials; warp covers 128 i, lane = j
    {
        unsigned long long acc[4] = {0ull, 0ull, 0ull, 0ull};
        int i0 = warp * 128;
        #pragma unroll 4
        for (int i = i0; i < i0 + 128; i++) {
            float wv = w1[i * 32 + lane];
            unsigned long long wp = pk2(wv, wv);
            const unsigned long long* xp = (const unsigned long long*)&xnT[i * 8];
            fma2(acc[0], wp, xp[0]);
            fma2(acc[1], wp, xp[1]);
            fma2(acc[2], wp, xp[2]);
            fma2(acc[3], wp, xp[3]);
        }
        #pragma unroll
        for (int rp = 0; rp < 4; rp++) {
            float a, bv; upk2(acc[rp], a, bv);
            part[warp * 256 + (2 * rp) * 32 + lane] = a;
            part[warp * 256 + (2 * rp + 1) * 32 + lane] = bv;
        }
    }
    __syncthreads();

    // ---- reduce + GELU: thread = (r=warp, j=lane)
    {
        float h = b1[lane];
        #pragma unroll
        for (int w = 0; w < 8; w++) h += part[w * 256 + warp * 32 + lane];
        hs[warp * 32 + lane] = 0.5f * h * (1.0f + erff(h * 0.70710678118654752f));
    }
    __syncthreads();

    // ---- GEMM2 + residual
    #pragma unroll
    for (int u = 0; u < 4; u++) {
        int i = tid + u * 256;
        float acc[8];
        #pragma unroll
        for (int r = 0; r < 8; r++) acc[r] = g_aff0[(R0 + r) * 1024 + i];
        float bb = b2[i];
        #pragma unroll 8
        for (int j = 0; j < 32; j++) {
            float wv = w2[j * 1024 + i];
            #pragma unroll
            for (int r = 0; r < 8; r++) acc[r] = fmaf(hs[r * 32 + j], wv, acc[r]);
        }
        #pragma unroll
        for (int r = 0; r < 8; r++) g_y1[(R0 + r) * 1024 + i] = acc[r] + bb;
    }
}

// =============================================================================
// Kernel 3: p_conv 1024ch -> 1, 3x3 SAME over (P,P); float4 channel groups.
// =============================================================================
__global__ __launch_bounds__(256) void k3_pconv(
    const float* __restrict__ pw, const float* __restrict__ pb,
    float* __restrict__ out)
{
    __shared__ float red[8];
    const int tid = threadIdx.x;
    const int bi = blockIdx.x;
    const int b = bi / LL, l = bi % LL;
    const int p1 = l / PP, p2 = l % PP;
    const int ch = tid * 4;

    float wreg[9][4];
    #pragma unroll
    for (int tap = 0; tap < 9; tap++)
        #pragma unroll
        for (int m = 0; m < 4; m++) wreg[tap][m] = pw[(ch + m) * 9 + tap];

    float4 a = make_float4(0.f, 0.f, 0.f, 0.f);
    #pragma unroll
    for (int dy = 0; dy < 3; dy++) {
        int y = p1 + dy - 1;
        if ((unsigned)y >= (unsigned)PP) continue;
        #pragma unroll
        for (int dx = 0; dx < 3; dx++) {
            int x = p2 + dx - 1;
            if ((unsigned)x >= (unsigned)PP) continue;
            const float4 row = *(const float4*)&g_y1[((size_t)b * LL + y * PP + x) * 1024 + ch];
            int tap = dy * 3 + dx;
            a.x = fmaf(row.x, wreg[tap][0], a.x);
            a.y = fmaf(row.y, wreg[tap][1], a.y);
            a.z = fmaf(row.z, wreg[tap][2], a.z);
            a.w = fmaf(row.w, wreg[tap][3], a.w);
        }
    }
    float s = a.x + a.y + a.z + a.w;
    #pragma unroll
    for (int o = 16; o > 0; o >>= 1) s += __shfl_xor_sync(0xffffffffu, s, o);
    if ((tid & 31) == 0) red[tid >> 5] = s;
    __syncthreads();
    if (tid == 0) {
        float t = pb[0];
        #pragma unroll
        for (int w = 0; w < 8; w++) t += red[w];
        out[bi] = t;
    }
}

// =============================================================================
// Kernel 4: spatial syno attention. Phase A: f32x2 + swizzled float4 LDS.
// Phase B collapsed: colsum(prob) -> single GEMV against v (coalesced stream).
// =============================================================================
__global__ __launch_bounds__(256) void k4_spatial(
    const float* __restrict__ kp, const float* __restrict__ vp,
    const float* __restrict__ syno)
{
    __shared__ __align__(16) float buf[32 * 256];   // swizzled [dd][64 groups] 32KB
    __shared__ __align__(16) float sc[16 * 200];    // scores/probs
    __shared__ __align__(16) float syT[32 * 16];    // swizzled syno chunk
    __shared__ float Pb[196];

    const int tid = threadIdx.x;
    const int bt = blockIdx.x;
    const float* kbase = kp + ((size_t)bt * 197 + 1) * DMODEL;
    const float* vbase = vp + ((size_t)bt * 197 + 1) * DMODEL;
    const float scale = 0.03608439182435161f;   // 1/sqrt(768)

    const int sg = tid / 49;       // s-tile group (s = sg*4+i)
    const int lg = tid % 49;       // l-tile group (l = lg*4+j)
    const bool act = (tid < 196);

    unsigned long long acc[4][2] = {{0ull,0ull},{0ull,0ull},{0ull,0ull},{0ull,0ull}};

    // ---- phase A: scores, d chunks of 32
    for (int dc = 0; dc < 24; dc++) {
        int d0 = dc * 32;
        if (tid < 128) {                      // syno loader (swizzled)
            int s = tid >> 3, dq = tid & 7;
            float4 sv = *(const float4*)&syno[s * DMODEL + d0 + dq * 4];
            int base = 4 * ((s >> 2) ^ (dq & 3)) + (s & 3);
            syT[(dq * 4 + 0) * 16 + base] = sv.x * scale;
            syT[(dq * 4 + 1) * 16 + base] = sv.y * scale;
            syT[(dq * 4 + 2) * 16 + base] = sv.z * scale;
            syT[(dq * 4 + 3) * 16 + base] = sv.w * scale;
        }
        for (int idx = tid; idx < 1568; idx += 256) {   // k loader (swizzled)
            int l = idx >> 3, kq = idx & 7;
            float4 kv = *(const float4*)&kbase[(size_t)l * DMODEL + d0 + kq * 4];
            int base = 4 * ((l >> 2) ^ kq) + (l & 3);
            buf[(kq * 4 + 0) * 256 + base] = kv.x;
            buf[(kq * 4 + 1) * 256 + base] = kv.y;
            buf[(kq * 4 + 2) * 256 + base] = kv.z;
            buf[(kq * 4 + 3) * 256 + base] = kv.w;
        }
        __syncthreads();
        if (act) {
            #pragma unroll 4
            for (int dd = 0; dd < 32; dd++) {
                float4 sa = *(const float4*)&syT[dd * 16 + 4 * (sg ^ ((dd >> 2) & 3))];
                float4 ka = *(const float4*)&buf[dd * 256 + 4 * (lg ^ ((dd >> 2) & 7))];
                unsigned long long k01 = pk2(ka.x, ka.y), k23 = pk2(ka.z, ka.w);
                unsigned long long s0 = pk2(sa.x, sa.x), s1 = pk2(sa.y, sa.y);
                unsigned long long s2 = pk2(sa.z, sa.z), s3 = pk2(sa.w, sa.w);
                fma2(acc[0][0], s0, k01); fma2(acc[0][1], s0, k23);
                fma2(acc[1][0], s1, k01); fma2(acc[1][1], s1, k23);
                fma2(acc[2][0], s2, k01); fma2(acc[2][1], s2, k23);
                fma2(acc[3][0], s3, k01); fma2(acc[3][1], s3, k23);
            }
        }
        __syncthreads();
    }
    if (act) {
        #pragma unroll
        for (int i = 0; i < 4; i++) {
            *(unsigned long long*)&sc[(sg * 4 + i) * 200 + lg * 4]     = acc[i][0];
            *(unsigned long long*)&sc[(sg * 4 + i) * 200 + lg * 4 + 2] = acc[i][1];
        }
    }
    __syncthreads();

    // ---- softmax over l per syno row (warp handles 2 rows)
    const int warp = tid >> 5, lane = tid & 31;
    #pragma unroll
    for (int si = 0; si < 2; si++) {
        int s = warp * 2 + si;
        float mx = -1e30f;
        for (int li = lane; li < 196; li += 32) mx = fmaxf(mx, sc[s * 200 + li]);
        #pragma unroll
        for (int o = 16; o > 0; o >>= 1) mx = fmaxf(mx, __shfl_xor_sync(0xffffffffu, mx, o));
        float sum = 0.f;
        for (int li = lane; li < 196; li += 32) {
            float e = __expf(sc[s * 200 + li] - mx);
            sc[s * 200 + li] = e; sum += e;
        }
        #pragma unroll
        for (int o = 16; o > 0; o >>= 1) sum += __shfl_xor_sync(0xffffffffu, sum, o);
        float inv = __fdividef(1.f, sum);
        for (int li = lane; li < 196; li += 32) sc[s * 200 + li] *= inv;
    }
    __syncthreads();

    // ---- colsum: P[l] = sum_s prob[s][l]  (mean over s commutes with mix)
    if (tid < 196) {
        float p = 0.f;
        #pragma unroll
        for (int s = 0; s < 16; s++) p += sc[s * 200 + tid];
        Pb[tid] = p;
    }
    __syncthreads();

    // ---- phase B: GEMV  out[w] = sum_l P[l] * v[l][w]  (coalesced v stream)
    if (tid < 192) {
        int w4 = tid * 4;
        float ax = 0.f, ay = 0.f, az = 0.f, aw = 0.f;
        for (int l = 0; l < 196; l += 4) {
            #pragma unroll
            for (int u = 0; u < 4; u++) {
                float p = Pb[l + u];
                float4 vv = *(const float4*)&vbase[(size_t)(l + u) * DMODEL + w4];
                ax = fmaf(p, vv.x, ax);
                ay = fmaf(p, vv.y, ay);
                az = fmaf(p, vv.z, az);
                aw = fmaf(p, vv.w, aw);
            }
        }
        *(float4*)&g_ypart[(size_t)bt * DMODEL + w4] = make_float4(ax, ay, az, aw);
    }
}

// =============================================================================
// Kernel 5: y_s[b][w] = sum_t partial / 512
// =============================================================================
__global__ __launch_bounds__(768) void k5_reduce(float* __restrict__ out)
{
    const int b = blockIdx.x, w = threadIdx.x;
    float s = 0.f;
    #pragma unroll
    for (int t = 0; t < 32; t++) s += g_ypart[((size_t)b * 32 + t) * DMODEL + w];
    out[b * DMODEL + w] = s * (1.f / 512.f);
}

// =============================================================================
extern "C" void kernel_launch(void* const* d_in, const int* in_sizes, int n_in,
                              void* d_out, int out_size)
{
    const float* q    = (const float*)d_in[0];
    const float* k    = (const float*)d_in[1];
    const float* v    = (const float*)d_in[2];
    const float* tw   = (const float*)d_in[3];
    const float* tb   = (const float*)d_in[4];
    const float* lng  = (const float*)d_in[5];
    const float* lnb  = (const float*)d_in[6];
    const float* w1   = (const float*)d_in[7];
    const float* b1   = (const float*)d_in[8];
    const float* w2   = (const float*)d_in[9];
    const float* b2   = (const float*)d_in[10];
    const float* pw   = (const float*)d_in[11];
    const float* pb   = (const float*)d_in[12];
    const float* syno = (const float*)d_in[13];
    float* out = (float*)d_out;

    k1_gram<<<BB * LL, 256>>>(q, k, tw, tb);
    k2_mlp<<<BB * LL / 8, 256>>>(lng, lnb, w1, b1, w2, b2);
    k3_pconv<<<BB * LL, 256>>>(pw, pb, out);
    k4_spatial<<<BB * TT, 256>>>(k, v, syno);
    k5_reduce<<<BB, 768>>>(out + BB * LL);
}